// round 16
// baseline (speedup 1.0000x reference)
#include <cuda_runtime.h>
#include <cuda_fp16.h>
#include <math.h>

#define DDIM 512        // feature dim per row
#define GROUPS 128      // groups per row
#define GPB 64          // groups per block (row split across 2 blocks)
#define KCODES 1024
#define KPAIRS 512
#define NTHREADS 128    // 4 warps
#define NWARPS 4
#define QCHUNK 64       // quads per warp (4 warps x 64 quads = 1024 codes)
#define IDXMASK 0x3FFu
#define PACKMASK 0xFFFFFC00u      // 10-bit (code) pack
#define QIDXMASK 0xFFu
#define QPACKMASK 0xFFFFFF00u     // 8-bit (quad) pack

__device__ float g_partials[1024];
__device__ int   g_count = 0;

__global__ void __launch_bounds__(NTHREADS) vq_fused_kernel(
    const float* __restrict__ fb,
    const float* __restrict__ emb,
    float* __restrict__ out,
    int n_elems, int nblocks, int out_size)
{
    // codebook as half2, interleaved by code pair: element j of pair p is
    // {e[2p][j], e[2p+1][j]}; one pair = 4 half2 = 16 B = one LDS.128.
    __shared__ __half2 s_codeh[KPAIRS][4];   // 8 KB
    __shared__ unsigned s_nh2[KPAIRS];       // half2 {nh0,nh1} per pair, 2 KB
    __shared__ float  s_row[DDIM];           // 2 KB (fp32: norm + exact loss)
    __shared__ float  s_m[GPB * NWARPS];     // packed chunk-partial best, 1 KB
    __shared__ float  s_red[NWARPS];
    __shared__ float  s_scale[2];
    __shared__ bool   s_last;

    const int tid = threadIdx.x;
    const int row  = blockIdx.x >> 1;
    const int half = blockIdx.x & 1;         // which 64-group half of the row
    const float* x = fb + (size_t)row * DDIM;

    // ---- load codebook, convert to interleaved half2, precompute nh ----
    #pragma unroll
    for (int kp = tid; kp < KPAIRS; kp += NTHREADS) {
        float4 e0 = reinterpret_cast<const float4*>(emb)[2 * kp];
        float4 e1 = reinterpret_cast<const float4*>(emb)[2 * kp + 1];
        s_codeh[kp][0] = __floats2half2_rn(e0.x, e1.x);
        s_codeh[kp][1] = __floats2half2_rn(e0.y, e1.y);
        s_codeh[kp][2] = __floats2half2_rn(e0.z, e1.z);
        s_codeh[kp][3] = __floats2half2_rn(e0.w, e1.w);
        float nh0 = -0.5f * (e0.x*e0.x + e0.y*e0.y + e0.z*e0.z + e0.w*e0.w);
        float nh1 = -0.5f * (e1.x*e1.x + e1.y*e1.y + e1.z*e1.z + e1.w*e1.w);
        __half2 nhh = __floats2half2_rn(nh0, nh1);
        s_nh2[kp] = *reinterpret_cast<unsigned*>(&nhh);
    }

    // ---- load row (fp32), sum of squares ----
    float ss = 0.0f;
    #pragma unroll
    for (int j = tid; j < DDIM; j += NTHREADS) {
        float v = x[j];
        s_row[j] = v;
        ss = fmaf(v, v, ss);
    }
    #pragma unroll
    for (int o = 16; o > 0; o >>= 1)
        ss += __shfl_xor_sync(0xffffffffu, ss, o);
    if ((tid & 31) == 0) s_red[tid >> 5] = ss;
    __syncthreads();

    if (tid == 0) {
        float tot = s_red[0] + s_red[1] + s_red[2] + s_red[3];
        float scale = sqrtf(tot);
        // FloatBiter (faithful fp32)
        float xc = fminf(fmaxf(scale + 1.0f, 1.0f), 16.0f);
        float lg = logf(xc) / 1.3862943611198906f;
        float s = 0.0f;
        #pragma unroll
        for (int i = 0; i < 8; i++) {
            float base = (float)(1 << i);
            int bit = ((int)floorf(lg * base)) & 1;
            s += (float)bit / base;
        }
        s_scale[0] = scale;
        s_scale[1] = powf(4.0f, s) - 1.0f;
    }
    __syncthreads();

    const float scale = s_scale[0];

    // ---- argmax of m_k = fn.e_k - 0.5||e_k||^2 over codes, fp16 scoring ----
    // 32 lanes x 2 groups = 64 groups; 4 warps each scan a 64-quad chunk.
    // HFMA2 scores a code PAIR per instruction. Quad tournament: 2 HMNMX2,
    // 1 cvt, 8-bit quad id packed into fp32 mantissa, FMNMX running max.
    const int gslot = tid & 31;
    const int kc = tid >> 5;
    const int gl0 = gslot * 2;            // local group (0..63)
    const int gg0 = half * GPB + gl0;     // global group in row

    float xr[2][4];
    __half2 xq[2][4];                     // {xr_j, xr_j}
    #pragma unroll
    for (int gg = 0; gg < 2; gg++) {
        float4 r4 = reinterpret_cast<const float4*>(s_row)[gg0 + gg];
        xr[gg][0] = r4.x / scale;   // IEEE div == fn (fp32 kept for loss)
        xr[gg][1] = r4.y / scale;
        xr[gg][2] = r4.z / scale;
        xr[gg][3] = r4.w / scale;
        #pragma unroll
        for (int j = 0; j < 4; j++)
            xq[gg][j] = __float2half2_rn(xr[gg][j]);
    }

    float best[2] = {-3e38f, -3e38f};
    const int qbeg = kc * QCHUNK;

    #pragma unroll 2
    for (int q = qbeg; q < qbeg + QCHUNK; q++) {
        // pair 2q and 2q+1: two LDS.128 + one LDS.64, all warp-uniform bcast
        uint4 av = *reinterpret_cast<const uint4*>(&s_codeh[2 * q][0]);
        uint4 bv = *reinterpret_cast<const uint4*>(&s_codeh[2 * q + 1][0]);
        uint2 nhv = *reinterpret_cast<const uint2*>(&s_nh2[2 * q]);
        __half2 a0 = *reinterpret_cast<__half2*>(&av.x);
        __half2 a1 = *reinterpret_cast<__half2*>(&av.y);
        __half2 a2 = *reinterpret_cast<__half2*>(&av.z);
        __half2 a3 = *reinterpret_cast<__half2*>(&av.w);
        __half2 b0 = *reinterpret_cast<__half2*>(&bv.x);
        __half2 b1 = *reinterpret_cast<__half2*>(&bv.y);
        __half2 b2 = *reinterpret_cast<__half2*>(&bv.z);
        __half2 b3 = *reinterpret_cast<__half2*>(&bv.w);
        __half2 nhA = *reinterpret_cast<__half2*>(&nhv.x);
        __half2 nhB = *reinterpret_cast<__half2*>(&nhv.y);
        #pragma unroll
        for (int gg = 0; gg < 2; gg++) {
            __half2 accA = __hfma2(xq[gg][0], a0, nhA);   // {m0, m1}
            accA = __hfma2(xq[gg][1], a1, accA);
            accA = __hfma2(xq[gg][2], a2, accA);
            accA = __hfma2(xq[gg][3], a3, accA);
            __half2 accB = __hfma2(xq[gg][0], b0, nhB);   // {m2, m3}
            accB = __hfma2(xq[gg][1], b1, accB);
            accB = __hfma2(xq[gg][2], b2, accB);
            accB = __hfma2(xq[gg][3], b3, accB);
            __half2 t = __hmax2(accA, accB);
            t = __hmax2(t, __lowhigh2highlow(t));         // both halves = max4
            float f = __half2float(__low2half(t));
            float pk = __uint_as_float((__float_as_uint(f) & QPACKMASK) | (unsigned)q);
            best[gg] = fmaxf(best[gg], pk);
        }
    }

    // ---- fix-up: rescan winning quad, pick code at 10-bit precision ----
    #pragma unroll
    for (int gg = 0; gg < 2; gg++) {
        const int bq = (int)(__float_as_uint(best[gg]) & QIDXMASK);
        uint4 av = *reinterpret_cast<const uint4*>(&s_codeh[2 * bq][0]);
        uint4 bv = *reinterpret_cast<const uint4*>(&s_codeh[2 * bq + 1][0]);
        uint2 nhv = *reinterpret_cast<const uint2*>(&s_nh2[2 * bq]);
        __half2 accA = __hfma2(xq[gg][0], *reinterpret_cast<__half2*>(&av.x),
                               *reinterpret_cast<__half2*>(&nhv.x));
        accA = __hfma2(xq[gg][1], *reinterpret_cast<__half2*>(&av.y), accA);
        accA = __hfma2(xq[gg][2], *reinterpret_cast<__half2*>(&av.z), accA);
        accA = __hfma2(xq[gg][3], *reinterpret_cast<__half2*>(&av.w), accA);
        __half2 accB = __hfma2(xq[gg][0], *reinterpret_cast<__half2*>(&bv.x),
                               *reinterpret_cast<__half2*>(&nhv.y));
        accB = __hfma2(xq[gg][1], *reinterpret_cast<__half2*>(&bv.y), accB);
        accB = __hfma2(xq[gg][2], *reinterpret_cast<__half2*>(&bv.z), accB);
        accB = __hfma2(xq[gg][3], *reinterpret_cast<__half2*>(&bv.w), accB);
        float f0 = __half2float(__low2half(accA));
        float f1 = __half2float(__high2half(accA));
        float f2 = __half2float(__low2half(accB));
        float f3 = __half2float(__high2half(accB));
        unsigned k0 = 4 * bq;
        float p0 = __uint_as_float((__float_as_uint(f0) & PACKMASK) | (k0 + 0));
        float p1 = __uint_as_float((__float_as_uint(f1) & PACKMASK) | (k0 + 1));
        float p2 = __uint_as_float((__float_as_uint(f2) & PACKMASK) | (k0 + 2));
        float p3 = __uint_as_float((__float_as_uint(f3) & PACKMASK) | (k0 + 3));
        float fix = fmaxf(fmaxf(p0, p1), fmaxf(p2, p3));
        s_m[(gl0 + gg) * NWARPS + kc] = fix;
    }
    __syncthreads();

    // ---- combine chunk partials: one group per thread (first 64 threads) ----
    float l = 0.0f;
    if (tid < GPB) {
        const int gl = tid;
        const int g = half * GPB + gl;
        float bm = fmaxf(fmaxf(s_m[gl * NWARPS + 0], s_m[gl * NWARPS + 1]),
                         fmaxf(s_m[gl * NWARPS + 2], s_m[gl * NWARPS + 3]));
        const int bx = (int)(__float_as_uint(bm) & IDXMASK);

        // exact fp32 embed for output + loss
        float4 e = __ldg(&reinterpret_cast<const float4*>(emb)[bx]);
        const float sq = s_scale[1];
        reinterpret_cast<float4*>(out + (size_t)row * DDIM)[g] =
            make_float4(e.x * sq, e.y * sq, e.z * sq, e.w * sq);

        // loss in exact fp32: sum (fqn - fn)^2
        float d0 = e.x - s_row[g * 4 + 0] / scale;
        float d1 = e.y - s_row[g * 4 + 1] / scale;
        float d2 = e.z - s_row[g * 4 + 2] / scale;
        float d3 = e.w - s_row[g * 4 + 3] / scale;
        l = d0*d0 + d1*d1 + d2*d2 + d3*d3;
    }
    // reduce l over first 2 warps (threads >= 64 contribute 0)
    #pragma unroll
    for (int o = 16; o > 0; o >>= 1)
        l += __shfl_xor_sync(0xffffffffu, l, o);
    __syncthreads();   // s_red reuse
    if ((tid & 31) == 0) s_red[tid >> 5] = l;
    __syncthreads();

    // ---- last-block fused loss reduction (deterministic fixed order) ----
    if (tid == 0) {
        g_partials[blockIdx.x] = s_red[0] + s_red[1];
        __threadfence();
        int prev = atomicAdd(&g_count, 1);
        s_last = (prev == nblocks - 1);
    }
    __syncthreads();

    if (s_last) {
        __threadfence();
        float v = 0.0f;
        #pragma unroll
        for (int i = 0; i < 8; i++)
            v += g_partials[tid + 128 * i];
        #pragma unroll
        for (int o = 16; o > 0; o >>= 1)
            v += __shfl_xor_sync(0xffffffffu, v, o);
        __syncthreads();
        if ((tid & 31) == 0) s_red[tid >> 5] = v;
        __syncthreads();
        if (tid == 0) {
            float loss = (s_red[0] + s_red[1] + s_red[2] + s_red[3]) / (float)n_elems;
            if (out_size >= n_elems + 1) out[n_elems] = loss;
            if (out_size >= n_elems + 2) out[n_elems + 1] = loss;
            g_count = 0;   // reset for next replay
        }
    }
}

extern "C" void kernel_launch(void* const* d_in, const int* in_sizes, int n_in,
                              void* d_out, int out_size)
{
    const float* fb  = (const float*)d_in[0];
    const float* emb = (const float*)d_in[1];
    float* out = (float*)d_out;

    int n = in_sizes[0];       // 262144
    int rows = n / DDIM;       // 512
    int nblocks = rows * 2;    // 1024 (two group-halves per row)

    vq_fused_kernel<<<nblocks, NTHREADS>>>(fb, emb, out, n, nblocks, out_size);
}

// round 17
// speedup vs baseline: 1.4782x; 1.4782x over previous
#include <cuda_runtime.h>
#include <cuda_fp16.h>
#include <math.h>

#define DDIM 512        // feature dim per row
#define GROUPS 128      // groups per row (one row per block)
#define KCODES 1024
#define NTHREADS 128    // 4 warps
#define NWARPS 4
#define NTILES_PER_WARP 32   // 4 warps x 32 ntiles x 8 codes = 1024 codes
#define IDXMASK 0x3FFu
#define PACKMASK 0xFFFFFC00u  // keep 13 mantissa bits, 10-bit code id in low bits

__device__ float g_partials[512];
__device__ int   g_count = 0;

__device__ __forceinline__ void mma_m16n8k8(
    float& d0, float& d1, float& d2, float& d3,
    unsigned a0, unsigned a1, unsigned b0)
{
    asm volatile(
        "mma.sync.aligned.m16n8k8.row.col.f32.f16.f16.f32 "
        "{%0,%1,%2,%3}, {%4,%5}, {%6}, {%7,%8,%9,%10};"
        : "=f"(d0), "=f"(d1), "=f"(d2), "=f"(d3)
        : "r"(a0), "r"(a1), "r"(b0),
          "f"(0.0f), "f"(0.0f), "f"(0.0f), "f"(0.0f));
}

__global__ void __launch_bounds__(NTHREADS) vq_fused_kernel(
    const float* __restrict__ fb,
    const float* __restrict__ emb,
    float* __restrict__ out,
    int n_elems, int nblocks, int out_size)
{
    // B matrix, n-major: s_B[n][k], k=0..3 = e (fp16), k=4 = -0.5||e||^2, k=5..7 = 0
    __shared__ __align__(16) __half s_B[KCODES * 8];   // 16 KB
    __shared__ __align__(16) float  s_row[DDIM];       // 2 KB
    __shared__ float  s_m[GROUPS * NWARPS];            // packed per-(group,warp) best, 2 KB
    __shared__ float  s_red[NWARPS];
    __shared__ float  s_scale[2];
    __shared__ bool   s_last;

    const int tid = threadIdx.x;
    const int row = blockIdx.x;
    const float* x = fb + (size_t)row * DDIM;

    // ---- convert codebook to fp16, fold nh into K=5th column ----
    #pragma unroll
    for (int k = tid; k < KCODES; k += NTHREADS) {
        float4 e = reinterpret_cast<const float4*>(emb)[k];
        float nh = -0.5f * (e.x*e.x + e.y*e.y + e.z*e.z + e.w*e.w);
        unsigned* dst = reinterpret_cast<unsigned*>(&s_B[k * 8]);
        __half2 h01 = __floats2half2_rn(e.x, e.y);
        __half2 h23 = __floats2half2_rn(e.z, e.w);
        __half2 h45 = __floats2half2_rn(nh, 0.0f);
        dst[0] = *reinterpret_cast<unsigned*>(&h01);
        dst[1] = *reinterpret_cast<unsigned*>(&h23);
        dst[2] = *reinterpret_cast<unsigned*>(&h45);
        dst[3] = 0u;
    }

    // ---- load row (fp32), sum of squares ----
    float ss = 0.0f;
    #pragma unroll
    for (int j = tid; j < DDIM; j += NTHREADS) {
        float v = x[j];
        s_row[j] = v;
        ss = fmaf(v, v, ss);
    }
    #pragma unroll
    for (int o = 16; o > 0; o >>= 1)
        ss += __shfl_xor_sync(0xffffffffu, ss, o);
    if ((tid & 31) == 0) s_red[tid >> 5] = ss;
    __syncthreads();

    if (tid == 0) {
        float tot = s_red[0] + s_red[1] + s_red[2] + s_red[3];
        float scale = sqrtf(tot);
        // FloatBiter (faithful fp32)
        float xc = fminf(fmaxf(scale + 1.0f, 1.0f), 16.0f);
        float lg = logf(xc) / 1.3862943611198906f;
        float s = 0.0f;
        #pragma unroll
        for (int i = 0; i < 8; i++) {
            float base = (float)(1 << i);
            int bit = ((int)floorf(lg * base)) & 1;
            s += (float)bit / base;
        }
        s_scale[0] = scale;
        s_scale[1] = powf(4.0f, s) - 1.0f;
    }
    __syncthreads();

    const float scale = s_scale[0];
    const int lane = tid & 31;
    const int wid = tid >> 5;
    const int qr = lane >> 2;    // fragment row within tile (0..7)
    const int qc = lane & 3;     // k-pair / n-pair selector (0..3)

    // ---- build A fragments: A[g][k] = fn[g][k] (k<4), 1.0 (k=4), 0 (k>4) ----
    // a0: row = mt*16+qr, cols 2qc..2qc+1 ; a1: row = mt*16+qr+8
    unsigned afrag[8][2];
    #pragma unroll
    for (int mt = 0; mt < 8; mt++) {
        #pragma unroll
        for (int h = 0; h < 2; h++) {
            const int g = mt * 16 + qr + 8 * h;
            float4 r4 = reinterpret_cast<const float4*>(s_row)[g];
            __half2 v;
            if (qc == 0)      v = __floats2half2_rn(r4.x / scale, r4.y / scale);
            else if (qc == 1) v = __floats2half2_rn(r4.z / scale, r4.w / scale);
            else if (qc == 2) v = __floats2half2_rn(1.0f, 0.0f);
            else              v = __floats2half2_rn(0.0f, 0.0f);
            afrag[mt][h] = *reinterpret_cast<unsigned*>(&v);
        }
    }

    // ---- tensor-core scan: warp covers ntiles [wid*32, wid*32+32) ----
    // Per thread, D gives scores for codes n = ntile*8 + 2qc + {0,1},
    // rows mt*16+qr and mt*16+qr+8. Running packed max per (mt, half).
    float bestLo[8], bestHi[8];
    #pragma unroll
    for (int mt = 0; mt < 8; mt++) { bestLo[mt] = -3e38f; bestHi[mt] = -3e38f; }

    const int ntbeg = wid * NTILES_PER_WARP;
    for (int nt = ntbeg; nt < ntbeg + NTILES_PER_WARP; nt++) {
        // B fragment: {B[2qc][n], B[2qc+1][n]} with n = nt*8 + qr  (conflict-free LDS.32)
        unsigned bfrag = *reinterpret_cast<const unsigned*>(&s_B[(nt * 8 + qr) * 8 + 2 * qc]);
        const unsigned idx0 = (unsigned)(nt * 8 + 2 * qc);
        #pragma unroll
        for (int mt = 0; mt < 8; mt++) {
            float d0, d1, d2, d3;
            mma_m16n8k8(d0, d1, d2, d3, afrag[mt][0], afrag[mt][1], bfrag);
            float p0 = __uint_as_float((__float_as_uint(d0) & PACKMASK) | idx0);
            float p1 = __uint_as_float((__float_as_uint(d1) & PACKMASK) | (idx0 + 1));
            bestLo[mt] = fmaxf(bestLo[mt], fmaxf(p0, p1));
            float p2 = __uint_as_float((__float_as_uint(d2) & PACKMASK) | idx0);
            float p3 = __uint_as_float((__float_as_uint(d3) & PACKMASK) | (idx0 + 1));
            bestHi[mt] = fmaxf(bestHi[mt], fmaxf(p2, p3));
        }
    }

    // ---- combine the 4 lanes (qc=0..3) that share each D-row ----
    #pragma unroll
    for (int mt = 0; mt < 8; mt++) {
        bestLo[mt] = fmaxf(bestLo[mt], __shfl_xor_sync(0xffffffffu, bestLo[mt], 1));
        bestLo[mt] = fmaxf(bestLo[mt], __shfl_xor_sync(0xffffffffu, bestLo[mt], 2));
        bestHi[mt] = fmaxf(bestHi[mt], __shfl_xor_sync(0xffffffffu, bestHi[mt], 1));
        bestHi[mt] = fmaxf(bestHi[mt], __shfl_xor_sync(0xffffffffu, bestHi[mt], 2));
    }
    if (qc == 0) {
        #pragma unroll
        for (int mt = 0; mt < 8; mt++) {
            s_m[(mt * 16 + qr) * NWARPS + wid]     = bestLo[mt];
            s_m[(mt * 16 + qr + 8) * NWARPS + wid] = bestHi[mt];
        }
    }
    __syncthreads();

    // ---- combine 4 warps: one group per thread (all 128 threads) ----
    float l = 0.0f;
    {
        const int g = tid;
        float bm = fmaxf(fmaxf(s_m[g * NWARPS + 0], s_m[g * NWARPS + 1]),
                         fmaxf(s_m[g * NWARPS + 2], s_m[g * NWARPS + 3]));
        const int bx = (int)(__float_as_uint(bm) & IDXMASK);

        // exact fp32 embed for output + loss
        float4 e = __ldg(&reinterpret_cast<const float4*>(emb)[bx]);
        const float sq = s_scale[1];
        reinterpret_cast<float4*>(out + (size_t)row * DDIM)[g] =
            make_float4(e.x * sq, e.y * sq, e.z * sq, e.w * sq);

        // loss in exact fp32: sum (fqn - fn)^2
        float d0 = e.x - s_row[g * 4 + 0] / scale;
        float d1 = e.y - s_row[g * 4 + 1] / scale;
        float d2 = e.z - s_row[g * 4 + 2] / scale;
        float d3 = e.w - s_row[g * 4 + 3] / scale;
        l = d0*d0 + d1*d1 + d2*d2 + d3*d3;
    }
    #pragma unroll
    for (int o = 16; o > 0; o >>= 1)
        l += __shfl_xor_sync(0xffffffffu, l, o);
    __syncthreads();   // s_red reuse
    if ((tid & 31) == 0) s_red[tid >> 5] = l;
    __syncthreads();

    // ---- last-block fused loss reduction (deterministic fixed order) ----
    if (tid == 0) {
        g_partials[row] = s_red[0] + s_red[1] + s_red[2] + s_red[3];
        __threadfence();
        int prev = atomicAdd(&g_count, 1);
        s_last = (prev == nblocks - 1);
    }
    __syncthreads();

    if (s_last) {
        __threadfence();
        float v = g_partials[tid] + g_partials[tid + 128]
                + g_partials[tid + 256] + g_partials[tid + 384];
        #pragma unroll
        for (int o = 16; o > 0; o >>= 1)
            v += __shfl_xor_sync(0xffffffffu, v, o);
        __syncthreads();
        if ((tid & 31) == 0) s_red[tid >> 5] = v;
        __syncthreads();
        if (tid == 0) {
            float loss = (s_red[0] + s_red[1] + s_red[2] + s_red[3]) / (float)n_elems;
            if (out_size >= n_elems + 1) out[n_elems] = loss;
            if (out_size >= n_elems + 2) out[n_elems + 1] = loss;
            g_count = 0;   // reset for next replay
        }
    }
}

extern "C" void kernel_launch(void* const* d_in, const int* in_sizes, int n_in,
                              void* d_out, int out_size)
{
    const float* fb  = (const float*)d_in[0];
    const float* emb = (const float*)d_in[1];
    float* out = (float*)d_out;

    int n = in_sizes[0];       // 262144
    int rows = n / DDIM;       // 512

    vq_fused_kernel<<<rows, NTHREADS>>>(fb, emb, out, n, rows, out_size);
}